// round 1
// baseline (speedup 1.0000x reference)
#include <cuda_runtime.h>
#include <math.h>

#define CUTOFF   1.5f
#define CUTOFF2  2.25f
#define NMAX     16384
#define NCCAP    15
#define NCMAX    (NCCAP*NCCAP*NCCAP + 8)   // 3383
#define SMAX     16

// ---------------- device scratch (no allocations allowed) ----------------
__device__ float  g_inv[9];      // inverse cell (row-major), frac_k = sum_m x_m * inv[m*3+k]
__device__ float  g_cellm[9];    // cell (row-major, rows = lattice vectors)
__device__ int    g_nc[3];
__device__ int    g_nctot;
__device__ double g_energy;
__device__ int    g_count[NCMAX];
__device__ int    g_startc[NCMAX];
__device__ int    g_cellid[NMAX];
__device__ int    g_rank[NMAX];
__device__ float4 g_spos[NMAX];  // sorted positions, w = species
__device__ int    g_orig[NMAX];  // sorted -> original index
__device__ int    g_scell[NMAX]; // sorted -> cell id (from binning pass, authoritative)

// ---------------- setup: invert cell, pick grid, zero energy ----------------
__global__ void k_setup(const float* __restrict__ cell) {
    if (threadIdx.x != 0 || blockIdx.x != 0) return;
    double c00=cell[0], c01=cell[1], c02=cell[2];
    double c10=cell[3], c11=cell[4], c12=cell[5];
    double c20=cell[6], c21=cell[7], c22=cell[8];
    double det = c00*(c11*c22 - c12*c21) - c01*(c10*c22 - c12*c20) + c02*(c10*c21 - c11*c20);
    double id = 1.0 / det;
    double i00=(c11*c22-c12*c21)*id, i01=(c02*c21-c01*c22)*id, i02=(c01*c12-c02*c11)*id;
    double i10=(c12*c20-c10*c22)*id, i11=(c00*c22-c02*c20)*id, i12=(c02*c10-c00*c12)*id;
    double i20=(c10*c21-c11*c20)*id, i21=(c01*c20-c00*c21)*id, i22=(c00*c11-c01*c10)*id;
    g_inv[0]=(float)i00; g_inv[1]=(float)i01; g_inv[2]=(float)i02;
    g_inv[3]=(float)i10; g_inv[4]=(float)i11; g_inv[5]=(float)i12;
    g_inv[6]=(float)i20; g_inv[7]=(float)i21; g_inv[8]=(float)i22;
    #pragma unroll
    for (int m = 0; m < 9; m++) g_cellm[m] = cell[m];
    // perpendicular width along frac axis k = 1/||inv[:,k]||
    double w0 = 1.0 / sqrt(i00*i00 + i10*i10 + i20*i20);
    double w1 = 1.0 / sqrt(i01*i01 + i11*i11 + i21*i21);
    double w2 = 1.0 / sqrt(i02*i02 + i12*i12 + i22*i22);
    int n0 = (int)floor(w0 / (double)CUTOFF);
    int n1 = (int)floor(w1 / (double)CUTOFF);
    int n2 = (int)floor(w2 / (double)CUTOFF);
    n0 = n0 < 1 ? 1 : (n0 > NCCAP ? NCCAP : n0);
    n1 = n1 < 1 ? 1 : (n1 > NCCAP ? NCCAP : n1);
    n2 = n2 < 1 ? 1 : (n2 > NCCAP ? NCCAP : n2);
    g_nc[0]=n0; g_nc[1]=n1; g_nc[2]=n2;
    g_nctot = n0*n1*n2;
    g_energy = 0.0;
}

__global__ void k_zero_counts() {
    int i = blockIdx.x * blockDim.x + threadIdx.x;
    if (i < NCMAX) g_count[i] = 0;
}

__device__ __forceinline__ void cell_coords(float px, float py, float pz,
                                            int ncx, int ncy, int ncz,
                                            int* cx, int* cy, int* cz) {
    float f0 = px*g_inv[0] + py*g_inv[3] + pz*g_inv[6];
    float f1 = px*g_inv[1] + py*g_inv[4] + pz*g_inv[7];
    float f2 = px*g_inv[2] + py*g_inv[5] + pz*g_inv[8];
    f0 -= floorf(f0); f1 -= floorf(f1); f2 -= floorf(f2);
    int a = (int)(f0 * (float)ncx); if (a >= ncx) a = ncx-1; if (a < 0) a = 0;
    int b = (int)(f1 * (float)ncy); if (b >= ncy) b = ncy-1; if (b < 0) b = 0;
    int c = (int)(f2 * (float)ncz); if (c >= ncz) c = ncz-1; if (c < 0) c = 0;
    *cx = a; *cy = b; *cz = c;
}

__global__ void k_bin(const float* __restrict__ pos, int n) {
    int i = blockIdx.x * blockDim.x + threadIdx.x;
    if (i >= n) return;
    int ncx = g_nc[0], ncy = g_nc[1], ncz = g_nc[2];
    float px = pos[3*i], py = pos[3*i+1], pz = pos[3*i+2];
    int cx, cy, cz;
    cell_coords(px, py, pz, ncx, ncy, ncz, &cx, &cy, &cz);
    int cid = (cz*ncy + cy)*ncx + cx;
    g_cellid[i] = cid;
    g_rank[i] = atomicAdd(&g_count[cid], 1);
}

// exclusive prefix sum over g_count[0..nctot) (nctot <= 4096), one block of 1024
__global__ void k_scan() {
    __shared__ int ssum[1024];
    int ntot = g_nctot;
    int t = threadIdx.x;
    int v[4]; int s = 0;
    #pragma unroll
    for (int k = 0; k < 4; k++) {
        int idx = t*4 + k;
        v[k] = (idx < ntot) ? g_count[idx] : 0;
        s += v[k];
    }
    ssum[t] = s;
    __syncthreads();
    for (int off = 1; off < 1024; off <<= 1) {
        int x = (t >= off) ? ssum[t-off] : 0;
        __syncthreads();
        ssum[t] += x;
        __syncthreads();
    }
    int excl = (t == 0) ? 0 : ssum[t-1];
    #pragma unroll
    for (int k = 0; k < 4; k++) {
        int idx = t*4 + k;
        if (idx < ntot) g_startc[idx] = excl;
        excl += v[k];
    }
}

__global__ void k_scatter(const float* __restrict__ pos, const int* __restrict__ spec, int n) {
    int i = blockIdx.x * blockDim.x + threadIdx.x;
    if (i >= n) return;
    int cid = g_cellid[i];
    int dst = g_startc[cid] + g_rank[i];
    g_spos[dst]  = make_float4(pos[3*i], pos[3*i+1], pos[3*i+2], (float)spec[i]);
    g_orig[dst]  = i;
    g_scell[dst] = cid;
}

// one warp per atom, one lane per neighbor cell (27 of 32 lanes)
__global__ void __launch_bounds__(128) k_force(
    const float* __restrict__ sig, const float* __restrict__ eps,
    const float* __restrict__ alp, float* __restrict__ out, int n, int S) {
    __shared__ float s_sig[SMAX*SMAX], s_eps[SMAX*SMAX], s_alp[SMAX*SMAX];
    int t = threadIdx.x;
    int ss = S*S;
    for (int k = t; k < ss; k += blockDim.x) {
        s_sig[k] = sig[k]; s_eps[k] = eps[k]; s_alp[k] = alp[k];
    }
    __syncthreads();

    int warp = t >> 5, lane = t & 31;
    int a = blockIdx.x * 4 + warp;
    float fx = 0.f, fy = 0.f, fz = 0.f, en = 0.f;

    if (a < n) {
        float4 pa = g_spos[a];
        int si = (int)pa.w;
        int ncx = g_nc[0], ncy = g_nc[1], ncz = g_nc[2];
        int cid_a = g_scell[a];
        int cx = cid_a % ncx;
        int cy = (cid_a / ncx) % ncy;
        int cz = cid_a / (ncx*ncy);

        if (lane < 27) {
            int ox = lane % 3 - 1;
            int oy = (lane / 3) % 3 - 1;
            int oz = lane / 9 - 1;
            int rx = cx + ox, ry = cy + oy, rz = cz + oz;
            int wx = 0, wy = 0, wz = 0;
            if (rx < 0) { rx += ncx; wx = -1; } else if (rx >= ncx) { rx -= ncx; wx = 1; }
            if (ry < 0) { ry += ncy; wy = -1; } else if (ry >= ncy) { ry -= ncy; wy = 1; }
            if (rz < 0) { rz += ncz; wz = -1; } else if (rz >= ncz) { rz -= ncz; wz = 1; }
            float shx = wx*g_cellm[0] + wy*g_cellm[3] + wz*g_cellm[6];
            float shy = wx*g_cellm[1] + wy*g_cellm[4] + wz*g_cellm[7];
            float shz = wx*g_cellm[2] + wy*g_cellm[5] + wz*g_cellm[8];
            int cid = (rz*ncy + ry)*ncx + rx;
            int st  = g_startc[cid];
            int cnt = g_count[cid];
            float bx = shx - pa.x, by = shy - pa.y, bz = shz - pa.z;
            for (int m = 0; m < cnt; m++) {
                float4 pb = g_spos[st + m];
                float dx = pb.x + bx;
                float dy = pb.y + by;
                float dz = pb.z + bz;
                float r2 = dx*dx + dy*dy + dz*dz;
                if (r2 < CUTOFF2 && r2 > 1e-12f) {
                    float r = sqrtf(r2);
                    int sj = (int)pb.w;
                    int idx = si*S + sj;
                    float sg = s_sig[idx];
                    float f = 1.0f - r/sg;
                    if (f > 0.0f) {
                        float ep = s_eps[idx];
                        float al = s_alp[idx];
                        float pw = powf(f, al - 1.0f);   // f^(alpha-1)
                        en += ep/al * f * pw;            // eps/alpha * f^alpha
                        float coef = ep * pw / (sg * r);
                        fx -= coef * dx;
                        fy -= coef * dy;
                        fz -= coef * dz;
                    }
                }
            }
        }
    }
    // warp reduction over the 27 lanes (idle lanes hold zeros)
    #pragma unroll
    for (int off = 16; off; off >>= 1) {
        fx += __shfl_down_sync(0xffffffffu, fx, off);
        fy += __shfl_down_sync(0xffffffffu, fy, off);
        fz += __shfl_down_sync(0xffffffffu, fz, off);
        en += __shfl_down_sync(0xffffffffu, en, off);
    }
    __shared__ float blk_e[4];
    if (lane == 0) {
        if (a < n) {
            int o = g_orig[a];
            out[1 + 3*o + 0] = fx;
            out[1 + 3*o + 1] = fy;
            out[1 + 3*o + 2] = fz;
        }
        blk_e[warp] = (a < n) ? en : 0.0f;
    }
    __syncthreads();
    if (t == 0) {
        double s = (double)blk_e[0] + (double)blk_e[1] + (double)blk_e[2] + (double)blk_e[3];
        atomicAdd(&g_energy, s);
    }
}

__global__ void k_final(float* __restrict__ out) {
    if (threadIdx.x == 0 && blockIdx.x == 0)
        out[0] = (float)(0.5 * g_energy);
}

// ---------------- launch ----------------
extern "C" void kernel_launch(void* const* d_in, const int* in_sizes, int n_in,
                              void* d_out, int out_size) {
    const float* pos  = (const float*)d_in[0];
    const float* cell = (const float*)d_in[1];
    const float* sig  = (const float*)d_in[2];
    const float* eps  = (const float*)d_in[3];
    const float* alp  = (const float*)d_in[4];
    const int*   spec = (const int*)  d_in[5];
    int n  = in_sizes[5];            // N atoms
    int ss = in_sizes[2];            // S*S
    int S = 1; while (S*S < ss) S++;
    float* out = (float*)d_out;

    k_setup<<<1, 32>>>(cell);
    k_zero_counts<<<(NCMAX + 511)/512, 512>>>();
    k_bin<<<(n + 255)/256, 256>>>(pos, n);
    k_scan<<<1, 1024>>>();
    k_scatter<<<(n + 255)/256, 256>>>(pos, spec, n);
    k_force<<<(n + 3)/4, 128>>>(sig, eps, alp, out, n, S);
    k_final<<<1, 1>>>(out);
}

// round 2
// speedup vs baseline: 1.2003x; 1.2003x over previous
#include <cuda_runtime.h>
#include <math.h>

#define CUTOFF   1.5f
#define CUTOFF2  2.25f
#define NMAX     16384
#define NCCAP    15
#define NCMAX    (NCCAP*NCCAP*NCCAP + 9)   // 3384
#define SMAX     16

// ---------------- device scratch (no allocations allowed) ----------------
__device__ float        g_cellm[9];     // cell (row-major, rows = lattice vectors)
__device__ int          g_nc[3];
__device__ int          g_startc[NCMAX];
__device__ int          g_count[NCMAX];
__device__ float4       g_spos[NMAX];   // sorted positions, w = species
__device__ int          g_orig[NMAX];   // sorted -> original index
__device__ int          g_scell[NMAX];  // sorted -> cell id
__device__ float4       g_tbl[SMAX*SMAX]; // (1/sig, eps/alp, alp-1, eps/sig)
__device__ double       g_energy;
__device__ unsigned int g_done;

// =======================================================================
// k_prep: setup + zero + bin + block-scan + scatter + tables. ONE block.
// =======================================================================
__global__ void __launch_bounds__(1024) k_prep(
    const float* __restrict__ pos, const float* __restrict__ cell,
    const float* __restrict__ sig, const float* __restrict__ eps,
    const float* __restrict__ alp, const int* __restrict__ spec,
    int n, int S)
{
    __shared__ float s_inv[9];
    __shared__ int   s_ncs[4];        // ncx, ncy, ncz, nctot
    __shared__ int   s_cnt[NCMAX];
    __shared__ int   s_start[NCMAX];
    __shared__ int   s_wsum[32];

    int t = threadIdx.x;
    int lane = t & 31, warp = t >> 5;

    // zero shared counts
    for (int k = t; k < NCMAX; k += 1024) s_cnt[k] = 0;

    // per-pair tables (independent of setup)
    int ss = S * S;
    if (t < ss) {
        float sg = sig[t], ep = eps[t], al = alp[t];
        g_tbl[t] = make_float4(1.0f/sg, ep/al, al - 1.0f, ep/sg);
    }

    // setup: inverse cell (fp32), grid dims
    if (t == 0) {
        float c00=cell[0], c01=cell[1], c02=cell[2];
        float c10=cell[3], c11=cell[4], c12=cell[5];
        float c20=cell[6], c21=cell[7], c22=cell[8];
        float det = c00*(c11*c22 - c12*c21) - c01*(c10*c22 - c12*c20) + c02*(c10*c21 - c11*c20);
        float id = 1.0f / det;
        float i00=(c11*c22-c12*c21)*id, i01=(c02*c21-c01*c22)*id, i02=(c01*c12-c02*c11)*id;
        float i10=(c12*c20-c10*c22)*id, i11=(c00*c22-c02*c20)*id, i12=(c02*c10-c00*c12)*id;
        float i20=(c10*c21-c11*c20)*id, i21=(c01*c20-c00*c21)*id, i22=(c00*c11-c01*c10)*id;
        s_inv[0]=i00; s_inv[1]=i01; s_inv[2]=i02;
        s_inv[3]=i10; s_inv[4]=i11; s_inv[5]=i12;
        s_inv[6]=i20; s_inv[7]=i21; s_inv[8]=i22;
        g_cellm[0]=c00; g_cellm[1]=c01; g_cellm[2]=c02;
        g_cellm[3]=c10; g_cellm[4]=c11; g_cellm[5]=c12;
        g_cellm[6]=c20; g_cellm[7]=c21; g_cellm[8]=c22;
        // perpendicular widths along frac axes = 1/||inv column||
        float w0 = rsqrtf(i00*i00 + i10*i10 + i20*i20);
        float w1 = rsqrtf(i01*i01 + i11*i11 + i21*i21);
        float w2 = rsqrtf(i02*i02 + i12*i12 + i22*i22);
        int n0 = (int)floorf(w0 / CUTOFF);
        int n1 = (int)floorf(w1 / CUTOFF);
        int n2 = (int)floorf(w2 / CUTOFF);
        n0 = n0 < 1 ? 1 : (n0 > NCCAP ? NCCAP : n0);
        n1 = n1 < 1 ? 1 : (n1 > NCCAP ? NCCAP : n1);
        n2 = n2 < 1 ? 1 : (n2 > NCCAP ? NCCAP : n2);
        s_ncs[0]=n0; s_ncs[1]=n1; s_ncs[2]=n2; s_ncs[3]=n0*n1*n2;
        g_nc[0]=n0; g_nc[1]=n1; g_nc[2]=n2;
        g_energy = 0.0;
        g_done = 0u;
    }
    __syncthreads();

    int ncx = s_ncs[0], ncy = s_ncs[1], ncz = s_ncs[2];

    // bin 4 atoms per thread (keep pos in regs for scatter)
    float px[4], py[4], pz[4];
    int   cid[4], rk[4];
    #pragma unroll
    for (int k = 0; k < 4; k++) {
        int i = t + 1024*k;
        cid[k] = -1;
        if (i < n) {
            float x = pos[3*i], y = pos[3*i+1], z = pos[3*i+2];
            px[k]=x; py[k]=y; pz[k]=z;
            float f0 = x*s_inv[0] + y*s_inv[3] + z*s_inv[6];
            float f1 = x*s_inv[1] + y*s_inv[4] + z*s_inv[7];
            float f2 = x*s_inv[2] + y*s_inv[5] + z*s_inv[8];
            f0 -= floorf(f0); f1 -= floorf(f1); f2 -= floorf(f2);
            int a = (int)(f0 * (float)ncx); a = a >= ncx ? ncx-1 : (a < 0 ? 0 : a);
            int b = (int)(f1 * (float)ncy); b = b >= ncy ? ncy-1 : (b < 0 ? 0 : b);
            int c = (int)(f2 * (float)ncz); c = c >= ncz ? ncz-1 : (c < 0 ? 0 : c);
            int cc = (c*ncy + b)*ncx + a;
            cid[k] = cc;
            rk[k] = atomicAdd(&s_cnt[cc], 1);
        }
    }
    __syncthreads();

    // shuffle-based block exclusive scan over NCMAX cells, 4 cells/thread
    int v0=0, v1=0, v2=0, v3=0;
    int base = t*4;
    if (base+0 < NCMAX) v0 = s_cnt[base+0];
    if (base+1 < NCMAX) v1 = s_cnt[base+1];
    if (base+2 < NCMAX) v2 = s_cnt[base+2];
    if (base+3 < NCMAX) v3 = s_cnt[base+3];
    int msum = v0+v1+v2+v3;
    int inc = msum;
    #pragma unroll
    for (int o = 1; o < 32; o <<= 1) {
        int x = __shfl_up_sync(0xffffffffu, inc, o);
        if (lane >= o) inc += x;
    }
    if (lane == 31) s_wsum[warp] = inc;
    __syncthreads();
    if (warp == 0) {
        int w = s_wsum[lane];
        #pragma unroll
        for (int o = 1; o < 32; o <<= 1) {
            int x = __shfl_up_sync(0xffffffffu, w, o);
            if (lane >= o) w += x;
        }
        s_wsum[lane] = w;   // inclusive
    }
    __syncthreads();
    int excl = inc - msum + (warp ? s_wsum[warp-1] : 0);
    if (base+0 < NCMAX) s_start[base+0] = excl;            excl += v0;
    if (base+1 < NCMAX) s_start[base+1] = excl;            excl += v1;
    if (base+2 < NCMAX) s_start[base+2] = excl;            excl += v2;
    if (base+3 < NCMAX) s_start[base+3] = excl;
    __syncthreads();

    // publish cell tables to global
    for (int k = t; k < NCMAX; k += 1024) {
        g_startc[k] = s_start[k];
        g_count[k]  = s_cnt[k];
    }

    // scatter
    #pragma unroll
    for (int k = 0; k < 4; k++) {
        int i = t + 1024*k;
        if (i < n && cid[k] >= 0) {
            int dst = s_start[cid[k]] + rk[k];
            g_spos[dst]  = make_float4(px[k], py[k], pz[k], (float)spec[i]);
            g_orig[dst]  = i;
            g_scell[dst] = cid[k];
        }
    }
}

// =======================================================================
// k_force: one warp per atom, one lane per neighbor cell (27/32).
// Last block writes the energy scalar.
// =======================================================================
__global__ void __launch_bounds__(256) k_force(
    float* __restrict__ out, int n, int S)
{
    __shared__ float4 s_tbl[SMAX*SMAX];
    __shared__ float  s_e[8];
    int t = threadIdx.x;
    int ss = S*S;
    for (int k = t; k < ss; k += 256) s_tbl[k] = g_tbl[k];
    __syncthreads();

    int warp = t >> 5, lane = t & 31;
    int a = blockIdx.x * 8 + warp;
    float fx = 0.f, fy = 0.f, fz = 0.f, en = 0.f;

    if (a < n) {
        float4 pa = g_spos[a];
        int si = (int)pa.w;
        int ncx = g_nc[0], ncy = g_nc[1], ncz = g_nc[2];
        int cid_a = g_scell[a];
        int cx = cid_a % ncx;
        int cy = (cid_a / ncx) % ncy;
        int cz = cid_a / (ncx*ncy);

        if (lane < 27) {
            int ox = lane % 3 - 1;
            int oy = (lane / 3) % 3 - 1;
            int oz = lane / 9 - 1;
            int rx = cx + ox, ry = cy + oy, rz = cz + oz;
            int wx = 0, wy = 0, wz = 0;
            if (rx < 0) { rx += ncx; wx = -1; } else if (rx >= ncx) { rx -= ncx; wx = 1; }
            if (ry < 0) { ry += ncy; wy = -1; } else if (ry >= ncy) { ry -= ncy; wy = 1; }
            if (rz < 0) { rz += ncz; wz = -1; } else if (rz >= ncz) { rz -= ncz; wz = 1; }
            float shx = wx*g_cellm[0] + wy*g_cellm[3] + wz*g_cellm[6];
            float shy = wx*g_cellm[1] + wy*g_cellm[4] + wz*g_cellm[7];
            float shz = wx*g_cellm[2] + wy*g_cellm[5] + wz*g_cellm[8];
            int cidn = (rz*ncy + ry)*ncx + rx;
            int st  = g_startc[cidn];
            int cnt = g_count[cidn];
            float bx = shx - pa.x, by = shy - pa.y, bz = shz - pa.z;
            int sBase = si * S;
            for (int m = 0; m < cnt; m++) {
                float4 pb = g_spos[st + m];
                float dx = pb.x + bx;
                float dy = pb.y + by;
                float dz = pb.z + bz;
                float r2 = fmaf(dx,dx, fmaf(dy,dy, dz*dz));
                if (r2 < CUTOFF2 && r2 > 1e-12f) {
                    float rinv = rsqrtf(r2);
                    float r = r2 * rinv;
                    float4 tb = s_tbl[sBase + (int)pb.w];
                    float f = fmaf(-r, tb.x, 1.0f);        // 1 - r/sig
                    if (f > 0.0f) {
                        float pw = __powf(f, tb.z);        // f^(alpha-1)
                        en = fmaf(tb.y * f, pw, en);       // eps/alpha * f^alpha
                        float coef = tb.w * pw * rinv;     // eps/sig * f^(a-1) / r
                        fx = fmaf(-coef, dx, fx);
                        fy = fmaf(-coef, dy, fy);
                        fz = fmaf(-coef, dz, fz);
                    }
                }
            }
        }
    }
    // warp reduction (idle lanes hold zeros)
    #pragma unroll
    for (int off = 16; off; off >>= 1) {
        fx += __shfl_down_sync(0xffffffffu, fx, off);
        fy += __shfl_down_sync(0xffffffffu, fy, off);
        fz += __shfl_down_sync(0xffffffffu, fz, off);
        en += __shfl_down_sync(0xffffffffu, en, off);
    }
    if (lane == 0) {
        if (a < n) {
            int o = g_orig[a];
            out[1 + 3*o + 0] = fx;
            out[1 + 3*o + 1] = fy;
            out[1 + 3*o + 2] = fz;
        }
        s_e[warp] = (a < n) ? en : 0.0f;
    }
    __syncthreads();
    if (t == 0) {
        double e = 0.0;
        #pragma unroll
        for (int w = 0; w < 8; w++) e += (double)s_e[w];
        atomicAdd(&g_energy, e);
        __threadfence();
        unsigned int d = atomicAdd(&g_done, 1u);
        if (d == gridDim.x - 1) {
            double tot = atomicAdd(&g_energy, 0.0);
            out[0] = (float)(0.5 * tot);
        }
    }
}

// ---------------- launch ----------------
extern "C" void kernel_launch(void* const* d_in, const int* in_sizes, int n_in,
                              void* d_out, int out_size) {
    const float* pos  = (const float*)d_in[0];
    const float* cell = (const float*)d_in[1];
    const float* sig  = (const float*)d_in[2];
    const float* eps  = (const float*)d_in[3];
    const float* alp  = (const float*)d_in[4];
    const int*   spec = (const int*)  d_in[5];
    int n  = in_sizes[5];
    int ss = in_sizes[2];
    int S = 1; while (S*S < ss) S++;
    float* out = (float*)d_out;

    k_prep<<<1, 1024>>>(pos, cell, sig, eps, alp, spec, n, S);
    k_force<<<(n + 7)/8, 256>>>(out, n, S);
}

// round 6
// speedup vs baseline: 1.8323x; 1.5265x over previous
#include <cuda_runtime.h>
#include <math.h>

#define CUTOFF   1.5f
#define CUTOFF2  2.25f
#define NMAX     16384
#define NCCAP    15
#define NCMAX    (NCCAP*NCCAP*NCCAP + 9)   // 3384
#define CAP      24                         // max atoms per cell (lambda~3)
#define MAXC     320                        // staged candidates per warp
#define FBLK     256                        // force block threads (8 warps)

// ---------------- device scratch (no allocations allowed) ----------------
__device__ float        g_cellm[9];          // cell matrix (rows = lattice vectors)
__device__ int          g_nc[3];
__device__ int          g_count[NCMAX];      // MUST be zero at kernel_launch entry
__device__ float4       g_cpos[NCMAX*CAP];   // padded per-cell atom lists (xyz + species)
__device__ int          g_cellid[NMAX];      // atom -> cell id
__device__ float4       g_tbl[64];           // (1/sig, eps/alp, alp-1, eps/sig)
__device__ float        g_part[4096];        // per-block energy partials
__device__ unsigned int g_done;              // MUST be zero at entry

// =======================================================================
// k_bin: tables + cell setup + bin atoms into padded cell lists.
// Every thread computes the (cheap) 3x3 inverse redundantly — no ordering.
// =======================================================================
__global__ void __launch_bounds__(128) k_bin(
    const float* __restrict__ pos, const float* __restrict__ cell,
    const float* __restrict__ sig, const float* __restrict__ eps,
    const float* __restrict__ alp, const int* __restrict__ spec,
    int n, int S)
{
    int i = blockIdx.x * blockDim.x + threadIdx.x;

    // species tables (block 0 only)
    if (blockIdx.x == 0 && threadIdx.x < S*S) {
        int t = threadIdx.x;
        float sg = sig[t], ep = eps[t], al = alp[t];
        g_tbl[t] = make_float4(1.0f/sg, ep/al, al - 1.0f, ep/sg);
    }

    // cell inverse + grid dims (all threads, registers only)
    float c00=cell[0], c01=cell[1], c02=cell[2];
    float c10=cell[3], c11=cell[4], c12=cell[5];
    float c20=cell[6], c21=cell[7], c22=cell[8];
    float det = c00*(c11*c22 - c12*c21) - c01*(c10*c22 - c12*c20) + c02*(c10*c21 - c11*c20);
    float id = 1.0f / det;
    float i00=(c11*c22-c12*c21)*id, i01=(c02*c21-c01*c22)*id, i02=(c01*c12-c02*c11)*id;
    float i10=(c12*c20-c10*c22)*id, i11=(c00*c22-c02*c20)*id, i12=(c02*c10-c00*c12)*id;
    float i20=(c10*c21-c11*c20)*id, i21=(c01*c20-c00*c21)*id, i22=(c00*c11-c01*c10)*id;
    float w0 = rsqrtf(i00*i00 + i10*i10 + i20*i20);
    float w1 = rsqrtf(i01*i01 + i11*i11 + i21*i21);
    float w2 = rsqrtf(i02*i02 + i12*i12 + i22*i22);
    int n0 = (int)floorf(w0 / CUTOFF); n0 = n0 < 1 ? 1 : (n0 > NCCAP ? NCCAP : n0);
    int n1 = (int)floorf(w1 / CUTOFF); n1 = n1 < 1 ? 1 : (n1 > NCCAP ? NCCAP : n1);
    int n2 = (int)floorf(w2 / CUTOFF); n2 = n2 < 1 ? 1 : (n2 > NCCAP ? NCCAP : n2);

    if (i == 0) {
        g_cellm[0]=c00; g_cellm[1]=c01; g_cellm[2]=c02;
        g_cellm[3]=c10; g_cellm[4]=c11; g_cellm[5]=c12;
        g_cellm[6]=c20; g_cellm[7]=c21; g_cellm[8]=c22;
        g_nc[0]=n0; g_nc[1]=n1; g_nc[2]=n2;
    }

    if (i < n) {
        float x = pos[3*i], y = pos[3*i+1], z = pos[3*i+2];
        float f0 = x*i00 + y*i10 + z*i20;
        float f1 = x*i01 + y*i11 + z*i21;
        float f2 = x*i02 + y*i12 + z*i22;
        f0 -= floorf(f0); f1 -= floorf(f1); f2 -= floorf(f2);
        int a = (int)(f0 * (float)n0); a = a >= n0 ? n0-1 : (a < 0 ? 0 : a);
        int b = (int)(f1 * (float)n1); b = b >= n1 ? n1-1 : (b < 0 ? 0 : b);
        int c = (int)(f2 * (float)n2); c = c >= n2 ? n2-1 : (c < 0 ? 0 : c);
        int cid = (c*n1 + b)*n0 + a;
        g_cellid[i] = cid;
        int r = atomicAdd(&g_count[cid], 1);
        if (r < CAP)
            g_cpos[cid*CAP + r] = make_float4(x, y, z, (float)spec[i]);
    }
}

// =======================================================================
// k_force: one warp per atom. Warp stages all candidate refs from the 27
// neighbor cells into shared, then all 32 lanes consume them with a
// UNIFORM trip count (shuffles unconditional -> no divergence deadlock).
// Last block reduces per-block energy partials and resets scratch state.
// =======================================================================
__global__ void __launch_bounds__(FBLK) k_force(
    const float* __restrict__ pos, const int* __restrict__ spec,
    float* __restrict__ out, int n, int S)
{
    __shared__ float4 s_tbl[64];
    __shared__ int    s_list[(FBLK/32)*MAXC];
    __shared__ float  s_e[FBLK/32];
    __shared__ float  s_red[FBLK];

    int t = threadIdx.x;
    int ss = S*S;
    if (t < ss) s_tbl[t] = g_tbl[t];
    __syncthreads();

    int warp = t >> 5, lane = t & 31;
    int a = blockIdx.x * (FBLK/32) + warp;
    float fx = 0.f, fy = 0.f, fz = 0.f, en = 0.f;

    if (a < n) {   // warp-uniform (a depends only on block/warp)
        float px = pos[3*a], py = pos[3*a+1], pz = pos[3*a+2];
        int si = spec[a];
        int ncx = g_nc[0], ncy = g_nc[1], ncz = g_nc[2];
        int cid_a = g_cellid[a];
        int cx = cid_a % ncx;
        int cy = (cid_a / ncx) % ncy;
        int cz = cid_a / (ncx*ncy);

        // per-lane neighbor cell (lanes 0..26)
        int   cnt = 0, cbase = 0;
        float bx = 0.f, by = 0.f, bz = 0.f;
        if (lane < 27) {
            int ox = lane % 3 - 1;
            int oy = (lane / 3) % 3 - 1;
            int oz = lane / 9 - 1;
            int rx = cx + ox, ry = cy + oy, rz = cz + oz;
            int wx = 0, wy = 0, wz = 0;
            if (rx < 0) { rx += ncx; wx = -1; } else if (rx >= ncx) { rx -= ncx; wx = 1; }
            if (ry < 0) { ry += ncy; wy = -1; } else if (ry >= ncy) { ry -= ncy; wy = 1; }
            if (rz < 0) { rz += ncz; wz = -1; } else if (rz >= ncz) { rz -= ncz; wz = 1; }
            bx = wx*g_cellm[0] + wy*g_cellm[3] + wz*g_cellm[6] - px;
            by = wx*g_cellm[1] + wy*g_cellm[4] + wz*g_cellm[7] - py;
            bz = wx*g_cellm[2] + wy*g_cellm[5] + wz*g_cellm[8] - pz;
            int cidn = (rz*ncy + ry)*ncx + rx;
            cnt = g_count[cidn];
            cnt = cnt > CAP ? CAP : cnt;
            cbase = cidn * CAP;
        }

        // warp exclusive scan of cnt
        int inc = cnt;
        #pragma unroll
        for (int o = 1; o < 32; o <<= 1) {
            int x = __shfl_up_sync(0xffffffffu, inc, o);
            if (lane >= o) inc += x;
        }
        int nc_tot = __shfl_sync(0xffffffffu, inc, 31);
        int myoff = inc - cnt;
        nc_tot = nc_tot > MAXC ? MAXC : nc_tot;

        // stage candidate refs: (slot index) | (cell lane << 20)
        int wbase = warp * MAXC;
        for (int m = 0; m < cnt; m++) {
            int q = myoff + m;
            if (q < MAXC) s_list[wbase + q] = (cbase + m) | (lane << 20);
        }
        __syncwarp();

        int sBase = si * S;
        // UNIFORM trip count: all lanes execute every iteration.
        for (int qb = 0; qb < nc_tot; qb += 32) {
            int  q     = qb + lane;
            bool valid = q < nc_tot;
            int  ref   = valid ? s_list[wbase + q] : 0;
            int  c     = valid ? (ref >> 20) : 0;
            // shuffles unconditional — executed by all lanes every iteration
            float fbx = __shfl_sync(0xffffffffu, bx, c);
            float fby = __shfl_sync(0xffffffffu, by, c);
            float fbz = __shfl_sync(0xffffffffu, bz, c);
            if (valid) {
                float4 pb = g_cpos[ref & 0xFFFFF];
                float dx = pb.x + fbx;
                float dy = pb.y + fby;
                float dz = pb.z + fbz;
                float r2 = fmaf(dx,dx, fmaf(dy,dy, dz*dz));
                if (r2 < CUTOFF2 && r2 > 1e-12f) {
                    float rinv = rsqrtf(r2);
                    float r = r2 * rinv;
                    float4 tb = s_tbl[sBase + (int)pb.w];
                    float f = fmaf(-r, tb.x, 1.0f);          // 1 - r/sig
                    if (f > 0.0f) {
                        float pw = __powf(f, tb.z);          // f^(alpha-1)
                        en = fmaf(tb.y * f, pw, en);         // eps/alpha * f^alpha
                        float coef = tb.w * pw * rinv;       // eps/sig * f^(a-1) / r
                        fx = fmaf(-coef, dx, fx);
                        fy = fmaf(-coef, dy, fy);
                        fz = fmaf(-coef, dz, fz);
                    }
                }
            }
        }
    }

    // warp reduction
    #pragma unroll
    for (int off = 16; off; off >>= 1) {
        fx += __shfl_down_sync(0xffffffffu, fx, off);
        fy += __shfl_down_sync(0xffffffffu, fy, off);
        fz += __shfl_down_sync(0xffffffffu, fz, off);
        en += __shfl_down_sync(0xffffffffu, en, off);
    }
    if (lane == 0) {
        if (a < n) {
            out[1 + 3*a + 0] = fx;
            out[1 + 3*a + 1] = fy;
            out[1 + 3*a + 2] = fz;
        }
        s_e[warp] = (a < n) ? en : 0.0f;
    }
    __syncthreads();
    if (t == 0) {
        float e = 0.f;
        #pragma unroll
        for (int w = 0; w < FBLK/32; w++) e += s_e[w];
        g_part[blockIdx.x] = e;
        __threadfence();
        unsigned int d = atomicAdd(&g_done, 1u);
        s_e[0] = (d == gridDim.x - 1) ? 1.0f : 0.0f;   // reuse as flag
    }
    __syncthreads();

    // last block: reduce partials, write energy, reset scratch state
    if (s_e[0] != 0.0f) {
        __threadfence();
        int nb = gridDim.x;
        float acc = 0.f;
        for (int k = t; k < nb; k += FBLK) acc += g_part[k];
        s_red[t] = acc;
        __syncthreads();
        for (int o = FBLK/2; o > 0; o >>= 1) {
            if (t < o) s_red[t] += s_red[t + o];
            __syncthreads();
        }
        if (t == 0) {
            out[0] = 0.5f * s_red[0];
            g_done = 0u;
        }
        // re-zero cell counts for the next graph replay
        for (int k = t; k < NCMAX; k += FBLK) g_count[k] = 0;
    }
}

// ---------------- launch ----------------
extern "C" void kernel_launch(void* const* d_in, const int* in_sizes, int n_in,
                              void* d_out, int out_size) {
    const float* pos  = (const float*)d_in[0];
    const float* cell = (const float*)d_in[1];
    const float* sig  = (const float*)d_in[2];
    const float* eps  = (const float*)d_in[3];
    const float* alp  = (const float*)d_in[4];
    const int*   spec = (const int*)  d_in[5];
    int n  = in_sizes[5];
    int ss = in_sizes[2];
    int S = 1; while (S*S < ss) S++;
    float* out = (float*)d_out;

    k_bin<<<(n + 127)/128, 128>>>(pos, cell, sig, eps, alp, spec, n, S);
    k_force<<<(n + FBLK/32 - 1)/(FBLK/32), FBLK>>>(pos, spec, out, n, S);
}

// round 7
// speedup vs baseline: 1.9135x; 1.0443x over previous
#include <cuda_runtime.h>
#include <math.h>

#define CUTOFF   1.5f
#define CUTOFF2  2.25f
#define NMAX     16384
#define NCCAP    15
#define NCMAX    (NCCAP*NCCAP*NCCAP + 9)   // 3384
#define CAP      24                         // max atoms per cell (lambda~3)
#define FBLK     128                        // force block threads (4 warps, 2 atoms)

// ---------------- device scratch (no allocations allowed) ----------------
__device__ float        g_cellm[9];          // cell matrix (rows = lattice vectors)
__device__ int          g_nc[3];
__device__ int          g_count[NCMAX];      // MUST be zero at kernel_launch entry
__device__ float4       g_cpos[NCMAX*CAP];   // padded per-cell atom lists (xyz + species)
__device__ float4       g_apos[NMAX];        // per-atom: xyz, w = spec + 8*(cx+16*cy+256*cz)
__device__ float4       g_tbl[64];           // (1/sig, eps/alp, alp-1, eps/sig)
__device__ float        g_part[4096];        // per-block energy partials
__device__ unsigned int g_done;              // MUST be zero at entry

// =======================================================================
// k_bin: tables + cell setup + bin atoms into padded cell lists.
// =======================================================================
__global__ void __launch_bounds__(128) k_bin(
    const float* __restrict__ pos, const float* __restrict__ cell,
    const float* __restrict__ sig, const float* __restrict__ eps,
    const float* __restrict__ alp, const int* __restrict__ spec,
    int n, int S)
{
    int i = blockIdx.x * blockDim.x + threadIdx.x;

    // species tables (block 0 only)
    if (blockIdx.x == 0 && threadIdx.x < S*S) {
        int t = threadIdx.x;
        float sg = sig[t], ep = eps[t], al = alp[t];
        g_tbl[t] = make_float4(1.0f/sg, ep/al, al - 1.0f, ep/sg);
    }

    // cell inverse + grid dims (all threads, registers only)
    float c00=cell[0], c01=cell[1], c02=cell[2];
    float c10=cell[3], c11=cell[4], c12=cell[5];
    float c20=cell[6], c21=cell[7], c22=cell[8];
    float det = c00*(c11*c22 - c12*c21) - c01*(c10*c22 - c12*c20) + c02*(c10*c21 - c11*c20);
    float id = 1.0f / det;
    float i00=(c11*c22-c12*c21)*id, i01=(c02*c21-c01*c22)*id, i02=(c01*c12-c02*c11)*id;
    float i10=(c12*c20-c10*c22)*id, i11=(c00*c22-c02*c20)*id, i12=(c02*c10-c00*c12)*id;
    float i20=(c10*c21-c11*c20)*id, i21=(c01*c20-c00*c21)*id, i22=(c00*c11-c01*c10)*id;
    float w0 = rsqrtf(i00*i00 + i10*i10 + i20*i20);
    float w1 = rsqrtf(i01*i01 + i11*i11 + i21*i21);
    float w2 = rsqrtf(i02*i02 + i12*i12 + i22*i22);
    int n0 = (int)floorf(w0 / CUTOFF); n0 = n0 < 1 ? 1 : (n0 > NCCAP ? NCCAP : n0);
    int n1 = (int)floorf(w1 / CUTOFF); n1 = n1 < 1 ? 1 : (n1 > NCCAP ? NCCAP : n1);
    int n2 = (int)floorf(w2 / CUTOFF); n2 = n2 < 1 ? 1 : (n2 > NCCAP ? NCCAP : n2);

    if (i == 0) {
        g_cellm[0]=c00; g_cellm[1]=c01; g_cellm[2]=c02;
        g_cellm[3]=c10; g_cellm[4]=c11; g_cellm[5]=c12;
        g_cellm[6]=c20; g_cellm[7]=c21; g_cellm[8]=c22;
        g_nc[0]=n0; g_nc[1]=n1; g_nc[2]=n2;
    }

    if (i < n) {
        float x = pos[3*i], y = pos[3*i+1], z = pos[3*i+2];
        float f0 = x*i00 + y*i10 + z*i20;
        float f1 = x*i01 + y*i11 + z*i21;
        float f2 = x*i02 + y*i12 + z*i22;
        f0 -= floorf(f0); f1 -= floorf(f1); f2 -= floorf(f2);
        int a = (int)(f0 * (float)n0); a = a >= n0 ? n0-1 : (a < 0 ? 0 : a);
        int b = (int)(f1 * (float)n1); b = b >= n1 ? n1-1 : (b < 0 ? 0 : b);
        int c = (int)(f2 * (float)n2); c = c >= n2 ? n2-1 : (c < 0 ? 0 : c);
        int cid = (c*n1 + b)*n0 + a;
        int sp = spec[i];
        g_apos[i] = make_float4(x, y, z, (float)(sp + 8*(a + 16*b + 256*c)));
        int r = atomicAdd(&g_count[cid], 1);
        if (r < CAP)
            g_cpos[cid*CAP + r] = make_float4(x, y, z, (float)sp);
    }
}

// =======================================================================
// k_force: TWO warps per atom (cells 0-13 / 14-26), 2 slots per cell
// across lanes, direct pipelined LDG (no staging). Partial forces
// combined in shared. Last block reduces energy + resets scratch.
// =======================================================================
__global__ void __launch_bounds__(FBLK) k_force(
    float* __restrict__ out, int n, int S)
{
    __shared__ float4 s_tbl[64];
    __shared__ float4 s_f[FBLK/32];
    __shared__ float  s_red[FBLK];

    int t = threadIdx.x;
    if (t < S*S) s_tbl[t] = g_tbl[t];
    __syncthreads();

    int warp = t >> 5, lane = t & 31;
    int aslot = (blockIdx.x * (FBLK/32) + warp);
    int a = aslot >> 1;          // atom index
    int h = aslot & 1;           // half: 0 -> cells 0..13, 1 -> cells 14..26
    float fx = 0.f, fy = 0.f, fz = 0.f, en = 0.f;

    if (a < n) {
        float4 pa = g_apos[a];
        int w  = (int)pa.w;
        int si = w & 7;
        int pk = w >> 3;
        int cx = pk & 15, cy = (pk >> 4) & 15, cz = pk >> 8;
        int ncx = g_nc[0], ncy = g_nc[1], ncz = g_nc[2];

        // lane -> (local cell, slot) without runtime division
        int ncell = h ? 13 : 14;
        int nlane = 2 * ncell;                  // 28 or 26 active lanes
        bool act  = lane < nlane;
        int li    = (lane < ncell) ? lane : (lane - ncell);
        int slot  = (lane < ncell) ? 0 : 1;
        int c     = h * 14 + li;                // 0..26

        int cnt = 0, cbase = 0;
        float bx = 0.f, by = 0.f, bz = 0.f;
        if (act) {
            int ox = c % 3 - 1;
            int oy = (c / 3) % 3 - 1;
            int oz = c / 9 - 1;
            int rx = cx + ox, ry = cy + oy, rz = cz + oz;
            int wx = 0, wy = 0, wz = 0;
            if (rx < 0) { rx += ncx; wx = -1; } else if (rx >= ncx) { rx -= ncx; wx = 1; }
            if (ry < 0) { ry += ncy; wy = -1; } else if (ry >= ncy) { ry -= ncy; wy = 1; }
            if (rz < 0) { rz += ncz; wz = -1; } else if (rz >= ncz) { rz -= ncz; wz = 1; }
            bx = wx*g_cellm[0] + wy*g_cellm[3] + wz*g_cellm[6] - pa.x;
            by = wx*g_cellm[1] + wy*g_cellm[4] + wz*g_cellm[7] - pa.y;
            bz = wx*g_cellm[2] + wy*g_cellm[5] + wz*g_cellm[8] - pa.z;
            int cidn = (rz*ncy + ry)*ncx + rx;
            cnt = g_count[cidn];
            cnt = cnt > CAP ? CAP : cnt;
            cbase = cidn * CAP;
        }

        int sBase = si * S;
        for (int m = slot; m < cnt; m += 2) {     // no warp-collective ops inside
            float4 pb = g_cpos[cbase + m];
            float dx = pb.x + bx;
            float dy = pb.y + by;
            float dz = pb.z + bz;
            float r2 = fmaf(dx,dx, fmaf(dy,dy, dz*dz));
            if (r2 < CUTOFF2 && r2 > 1e-12f) {
                float rinv = rsqrtf(r2);
                float r = r2 * rinv;
                float4 tb = s_tbl[sBase + (int)pb.w];
                float f = fmaf(-r, tb.x, 1.0f);          // 1 - r/sig
                if (f > 0.0f) {
                    float pw = __powf(f, tb.z);          // f^(alpha-1)
                    en = fmaf(tb.y * f, pw, en);         // eps/alpha * f^alpha
                    float coef = tb.w * pw * rinv;       // eps/sig * f^(a-1) / r
                    fx = fmaf(-coef, dx, fx);
                    fy = fmaf(-coef, dy, fy);
                    fz = fmaf(-coef, dz, fz);
                }
            }
        }
    }

    // warp reduction
    #pragma unroll
    for (int off = 16; off; off >>= 1) {
        fx += __shfl_down_sync(0xffffffffu, fx, off);
        fy += __shfl_down_sync(0xffffffffu, fy, off);
        fz += __shfl_down_sync(0xffffffffu, fz, off);
        en += __shfl_down_sync(0xffffffffu, en, off);
    }
    if (lane == 0) s_f[warp] = make_float4(fx, fy, fz, en);
    __syncthreads();

    // combine warp pairs -> per-atom force
    if (t < FBLK/64) {
        int aa = blockIdx.x * (FBLK/64) + t;
        if (aa < n) {
            float4 u = s_f[2*t], v = s_f[2*t+1];
            out[1 + 3*aa + 0] = u.x + v.x;
            out[1 + 3*aa + 1] = u.y + v.y;
            out[1 + 3*aa + 2] = u.z + v.z;
        }
    }
    if (t == 0) {
        float e = 0.f;
        #pragma unroll
        for (int w = 0; w < FBLK/32; w++) e += s_f[w].w;
        g_part[blockIdx.x] = e;
        __threadfence();
        unsigned int d = atomicAdd(&g_done, 1u);
        s_red[0] = (d == gridDim.x - 1) ? 1.0f : 0.0f;
    }
    __syncthreads();

    // last block: reduce partials, write energy, reset scratch state
    if (s_red[0] != 0.0f) {
        __threadfence();
        int nb = gridDim.x;
        float acc = 0.f;
        for (int k = t; k < nb; k += FBLK) acc += g_part[k];
        __syncthreads();
        s_red[t] = acc;
        __syncthreads();
        for (int o = FBLK/2; o > 0; o >>= 1) {
            if (t < o) s_red[t] += s_red[t + o];
            __syncthreads();
        }
        if (t == 0) {
            out[0] = 0.5f * s_red[0];
            g_done = 0u;
        }
        for (int k = t; k < NCMAX; k += FBLK) g_count[k] = 0;
    }
}

// ---------------- launch ----------------
extern "C" void kernel_launch(void* const* d_in, const int* in_sizes, int n_in,
                              void* d_out, int out_size) {
    const float* pos  = (const float*)d_in[0];
    const float* cell = (const float*)d_in[1];
    const float* sig  = (const float*)d_in[2];
    const float* eps  = (const float*)d_in[3];
    const float* alp  = (const float*)d_in[4];
    const int*   spec = (const int*)  d_in[5];
    int n  = in_sizes[5];
    int ss = in_sizes[2];
    int S = 1; while (S*S < ss) S++;
    float* out = (float*)d_out;

    k_bin<<<(n + 127)/128, 128>>>(pos, cell, sig, eps, alp, spec, n, S);
    int nslots = 2 * n;                       // 2 warps per atom
    k_force<<<(nslots + FBLK/32 - 1)/(FBLK/32), FBLK>>>(out, n, S);
}